// round 1
// baseline (speedup 1.0000x reference)
#include <cuda_runtime.h>
#include <math.h>
#include <stdint.h>

// GAT2: B=256, N=256, DIN=128, H=4, DH=128.
// Pipeline:
//   K1: h1 = x @ W1            (fp32 SGEMM, 65536x512, K=128)
//   K2: per-(b,h) attention via sorted threshold sweep (O(N*DH) instead of O(N^2*DH))
//   K3: LayerNorm + ELU + dot with W2 -> z[b,n]  (fused, y never materialized)
//   K4: layer-2 scalar attention per batch -> out[b,n]

#define Bsz 256
#define Nn  256
#define DIN 128
#define Hh  4
#define DHd 128
#define HD  512   // Hh*DHd

// ---- scratch (device globals: allocation-free per harness rules) ----
__device__ float g_h1[(size_t)Bsz * Nn * HD];    // 134 MB
__device__ float g_out1[(size_t)Bsz * Nn * HD];  // 134 MB
__device__ float g_z[Bsz * Nn];

// ============================================================================
// K1: SGEMM  g_h1[m,c] = sum_k X[m,k] * W[k,c],  M=65536, Ncols=512, K=128
// 128x128 block tile, BK=8, 256 threads, 8x8 microtile.
// ============================================================================
__global__ void __launch_bounds__(256) sgemm_k1(const float* __restrict__ X,
                                                const float* __restrict__ W) {
    __shared__ float As[8][128];   // transposed: As[k][m]
    __shared__ float Bs[8][128];
    const int tid = threadIdx.x;
    const int row0g = blockIdx.y << 7;
    const int col0g = blockIdx.x << 7;

    const int ar = tid >> 1;            // 0..127  (A row within tile)
    const int ak = (tid & 1) << 2;      // 0 or 4  (A k-offset)
    const int bk = tid >> 5;            // 0..7    (B k-row)
    const int bc = (tid & 31) << 2;     // 0..124  (B col)

    const int ty = tid >> 4, tx = tid & 15;
    const int rowc = ty << 3, colc = tx << 3;

    float acc[8][8] = {};

    for (int k0 = 0; k0 < 128; k0 += 8) {
        float4 av = *(const float4*)(X + (size_t)(row0g + ar) * 128 + k0 + ak);
        float4 bv = *(const float4*)(W + (size_t)(k0 + bk) * 512 + col0g + bc);
        __syncthreads();
        As[ak + 0][ar] = av.x; As[ak + 1][ar] = av.y;
        As[ak + 2][ar] = av.z; As[ak + 3][ar] = av.w;
        *(float4*)(&Bs[bk][bc]) = bv;
        __syncthreads();
#pragma unroll
        for (int kk = 0; kk < 8; ++kk) {
            float4 a0 = *(const float4*)(&As[kk][rowc]);
            float4 a1 = *(const float4*)(&As[kk][rowc + 4]);
            float4 b0 = *(const float4*)(&Bs[kk][colc]);
            float4 b1 = *(const float4*)(&Bs[kk][colc + 4]);
            float a[8] = {a0.x, a0.y, a0.z, a0.w, a1.x, a1.y, a1.z, a1.w};
            float bb[8] = {b0.x, b0.y, b0.z, b0.w, b1.x, b1.y, b1.z, b1.w};
#pragma unroll
            for (int i = 0; i < 8; ++i)
#pragma unroll
                for (int j = 0; j < 8; ++j)
                    acc[i][j] = fmaf(a[i], bb[j], acc[i][j]);
        }
    }

    float* o = g_h1 + (size_t)(row0g + rowc) * 512 + col0g + colc;
#pragma unroll
    for (int i = 0; i < 8; ++i) {
        *(float4*)(o + (size_t)i * 512)     = make_float4(acc[i][0], acc[i][1], acc[i][2], acc[i][3]);
        *(float4*)(o + (size_t)i * 512 + 4) = make_float4(acc[i][4], acc[i][5], acc[i][6], acc[i][7]);
    }
}

// ============================================================================
// K2: layer-1 attention, one block per (b, head). Threshold-sweep algorithm.
//   w_ij = exp(lrelu(ad_i + as_j))
//        = e^{ad_i} * e^{as_j}           if as_j > -ad_i
//        = e^{0.2 ad_i} * e^{0.2 as_j}   otherwise
//   Sweep senders(by as_j) & receivers(by -ad_i) merged-sorted ascending,
//   maintaining S_pos = sum p_j h_j over not-yet-passed senders, S_neg likewise.
// ============================================================================
__device__ __forceinline__ unsigned f2u_ord(float f) {
    unsigned u = __float_as_uint(f);
    return (u & 0x80000000u) ? ~u : (u | 0x80000000u);
}

#define HSTRIDE 132  // 128 + 4 pad: keeps 16B alignment, kills bank conflicts

__global__ void __launch_bounds__(256) gat1_attn(const float* __restrict__ att_src,
                                                 const float* __restrict__ att_dst) {
    const int b  = blockIdx.x >> 2;
    const int hh = blockIdx.x & 3;
    const int tid = threadIdx.x;

    extern __shared__ float sm[];
    float* hsm = sm;                         // 256*132
    float* pv  = hsm + 256 * HSTRIDE;        // 256  exp(as)
    float* qv  = pv + 256;                   // 256  exp(0.2 as)
    float* e1  = qv + 256;                   // 256  exp(ad)
    float* e2  = e1 + 256;                   // 256  exp(0.2 ad)
    float* asv = e2 + 256;                   // 256
    float* adv = asv + 256;                  // 256
    unsigned* keys = (unsigned*)(adv + 256); // 512
    unsigned* payl = keys + 512;             // 512
    float* srcv = (float*)(payl + 512);      // 128
    float* dstv = srcv + 128;                // 128

    if (tid < 128) {
        srcv[tid] = att_src[hh * 128 + tid];
        dstv[tid] = att_dst[hh * 128 + tid];
    }

    // load h[b, :, hh, :] tile (256 x 128) into smem
    const float* hbase = g_h1 + ((size_t)(b * 256) * 4 + hh) * 128;
    for (int idx = tid; idx < 256 * 32; idx += 256) {
        int j = idx >> 5, d4 = (idx & 31) << 2;
        float4 v = *(const float4*)(hbase + (size_t)j * 512 + d4);
        *(float4*)(hsm + j * HSTRIDE + d4) = v;
    }
    __syncthreads();

    // per-row dot products: as_j = h_j . att_src, ad_j = h_j . att_dst
    {
        int w = tid >> 5, lane = tid & 31;
        for (int r = 0; r < 32; ++r) {
            int j = (w << 5) + r;
            float s1 = 0.f, s2 = 0.f;
#pragma unroll
            for (int u = 0; u < 4; ++u) {
                float hv = hsm[j * HSTRIDE + (u << 5) + lane];
                s1 = fmaf(hv, srcv[(u << 5) + lane], s1);
                s2 = fmaf(hv, dstv[(u << 5) + lane], s2);
            }
#pragma unroll
            for (int o = 16; o > 0; o >>= 1) {
                s1 += __shfl_down_sync(0xFFFFFFFFu, s1, o);
                s2 += __shfl_down_sync(0xFFFFFFFFu, s2, o);
            }
            if (lane == 0) { asv[j] = s1; adv[j] = s2; }
        }
    }
    __syncthreads();

    {
        float a = asv[tid], d = adv[tid];
        pv[tid] = expf(a);        qv[tid] = expf(0.2f * a);
        e1[tid] = expf(d);        e2[tid] = expf(0.2f * d);
        keys[tid]       = f2u_ord(a);   payl[tid]       = (unsigned)tid;        // sender
        keys[256 + tid] = f2u_ord(-d);  payl[256 + tid] = (unsigned)(256 + tid); // receiver
    }

    // bitonic sort 512 (key asc), payload carried along
    for (unsigned k = 2; k <= 512; k <<= 1)
        for (unsigned j = k >> 1; j > 0; j >>= 1) {
            __syncthreads();
            for (int i = tid; i < 512; i += 256) {
                int ixj = i ^ (int)j;
                if (ixj > i) {
                    unsigned ka = keys[i], kb = keys[ixj];
                    bool up = ((i & (int)k) == 0);
                    if ((ka > kb) == up) {
                        keys[i] = kb; keys[ixj] = ka;
                        unsigned t = payl[i]; payl[i] = payl[ixj]; payl[ixj] = t;
                    }
                }
            }
        }
    __syncthreads();

    // sweep: thread d in [0,128) owns dim d; scalars kept redundantly. No syncs.
    if (tid < 128) {
        float Sp = 0.f, Ps = 0.f;
        for (int j = 0; j < 256; ++j) {
            float pj = pv[j];
            Sp = fmaf(pj, hsm[j * HSTRIDE + tid], Sp);
            Ps += pj;
        }
        float Sn = 0.f, Qs = 0.f;
        float* ob = g_out1 + ((size_t)(b * 256) * 4 + hh) * 128 + tid;
        for (int e = 0; e < 512; ++e) {
            unsigned pl = payl[e];
            if (pl < 256) {  // sender leaves pos-set, enters neg-set
                float pj = pv[pl], qj = qv[pl];
                float hv = hsm[pl * HSTRIDE + tid];
                Sp = fmaf(-pj, hv, Sp);
                Sn = fmaf(qj, hv, Sn);
                Ps -= pj; Qs += qj;
            } else {         // receiver: emit output row
                int i = (int)pl - 256;
                float c1 = e1[i], c2 = e2[i];
                float num = fmaf(c1, Sp, c2 * Sn);
                float den = fmaf(c1, Ps, c2 * Qs);
                ob[(size_t)i * 512] = num / den;
            }
        }
    }
}

// ============================================================================
// K3: per row (b,n): LayerNorm(out1 + b1) -> ELU -> dot W2 -> z.  128 threads.
// ============================================================================
__global__ void __launch_bounds__(128) ln_elu_z_kernel(const float* __restrict__ b1,
                                                       const float* __restrict__ gamma,
                                                       const float* __restrict__ beta,
                                                       const float* __restrict__ W2) {
    const int row = blockIdx.x;
    const int tid = threadIdx.x;
    const int lane = tid & 31, w = tid >> 5;
    __shared__ float red[16];

    const float* r = g_out1 + (size_t)row * 512;
    float4 v  = *(const float4*)(r + (tid << 2));
    float4 bb = *(const float4*)(b1 + (tid << 2));
    v.x += bb.x; v.y += bb.y; v.z += bb.z; v.w += bb.w;

    float s  = v.x + v.y + v.z + v.w;
    float sq = v.x * v.x + v.y * v.y + v.z * v.z + v.w * v.w;
#pragma unroll
    for (int o = 16; o > 0; o >>= 1) {
        s  += __shfl_down_sync(0xFFFFFFFFu, s, o);
        sq += __shfl_down_sync(0xFFFFFFFFu, sq, o);
    }
    if (!lane) { red[w] = s; red[8 + w] = sq; }
    __syncthreads();
    float st  = red[0] + red[1] + red[2] + red[3];
    float sqt = red[8] + red[9] + red[10] + red[11];
    float mu   = st * (1.0f / 512.0f);
    float var  = sqt * (1.0f / 512.0f) - mu * mu;
    float rstd = rsqrtf(var + 1e-5f);

    float4 g4 = *(const float4*)(gamma + (tid << 2));
    float4 be = *(const float4*)(beta + (tid << 2));
    float4 w4 = *(const float4*)(W2 + (tid << 2));

    float y0 = (v.x - mu) * rstd * g4.x + be.x; y0 = y0 > 0.f ? y0 : expm1f(y0);
    float y1 = (v.y - mu) * rstd * g4.y + be.y; y1 = y1 > 0.f ? y1 : expm1f(y1);
    float y2 = (v.z - mu) * rstd * g4.z + be.z; y2 = y2 > 0.f ? y2 : expm1f(y2);
    float y3 = (v.w - mu) * rstd * g4.w + be.w; y3 = y3 > 0.f ? y3 : expm1f(y3);

    float acc = y0 * w4.x + y1 * w4.y + y2 * w4.z + y3 * w4.w;
#pragma unroll
    for (int o = 16; o > 0; o >>= 1) acc += __shfl_down_sync(0xFFFFFFFFu, acc, o);
    __syncthreads();
    if (!lane) red[w] = acc;
    __syncthreads();
    if (!tid) g_z[row] = red[0] + red[1] + red[2] + red[3];
}

// ============================================================================
// K4: layer-2 attention (scalar features), one block per batch b.
// ============================================================================
__global__ void __launch_bounds__(256) gat2_attn_kernel(const float* __restrict__ s_src,
                                                        const float* __restrict__ s_dst,
                                                        const float* __restrict__ b2,
                                                        float* __restrict__ out) {
    const int b = blockIdx.x;
    const int tid = threadIdx.x;
    __shared__ float zs[256], asx[256];
    float zv = g_z[b * 256 + tid];
    float ssc = s_src[0], sdc = s_dst[0];
    zs[tid] = zv;
    asx[tid] = zv * ssc;
    __syncthreads();
    float adi = zv * sdc;
    float num = 0.f, den = 0.f;
    for (int j = 0; j < 256; ++j) {
        float e = adi + asx[j];
        e = e > 0.f ? e : 0.2f * e;
        float wgt = expf(e);
        num = fmaf(wgt, zs[j], num);
        den += wgt;
    }
    out[b * 256 + tid] = num / den + b2[0];
}

// ============================================================================
// launch
// ============================================================================
extern "C" void kernel_launch(void* const* d_in, const int* in_sizes, int n_in,
                              void* d_out, int out_size) {
    const float* x     = (const float*)d_in[0];
    // d_in[1] = adj (ignored by reference; graph fully connected)
    const float* W1    = (const float*)d_in[2];
    const float* as1   = (const float*)d_in[3];
    const float* ad1   = (const float*)d_in[4];
    const float* b1    = (const float*)d_in[5];
    const float* gamma = (const float*)d_in[6];
    const float* beta  = (const float*)d_in[7];
    const float* W2    = (const float*)d_in[8];
    const float* as2   = (const float*)d_in[9];
    const float* ad2   = (const float*)d_in[10];
    const float* b2    = (const float*)d_in[11];
    float* out = (float*)d_out;

    const int smem_attn = (256 * HSTRIDE + 6 * 256 + 1024 + 256) * 4;  // 146432 B
    cudaFuncSetAttribute(gat1_attn, cudaFuncAttributeMaxDynamicSharedMemorySize, smem_attn);

    sgemm_k1<<<dim3(4, 512), 256>>>(x, W1);
    gat1_attn<<<Bsz * Hh, 256, smem_attn>>>(as1, ad1);
    ln_elu_z_kernel<<<Bsz * Nn, 128>>>(b1, gamma, beta, W2);
    gat2_attn_kernel<<<Bsz, 256>>>(as2, ad2, b2, out);
}

// round 4
// speedup vs baseline: 1.1367x; 1.1367x over previous
#include <cuda_runtime.h>
#include <cuda_bf16.h>
#include <math.h>
#include <stdint.h>

// GAT2: B=256, N=256, DIN=128, H=4, DH=128.
//   conv_x/conv_w: split fp32 -> bf16 hi/lo, packed K=384 (x*W = xh*Wh + xh*Wl + xl*Wh)
//   K1: mma.sync (HMMA) bf16 GEMM 65536x512, K=384, fp32 accum.
//   K2: per-(b,h) attention via sorted threshold sweep (O(N*DH))
//   K3: LayerNorm + ELU + dot W2 -> z
//   K4: layer-2 scalar attention

#define Bsz 256
#define Nn  256
#define Hh  4
#define HD  512
#define KP  384
#define MTOT 65536

__device__ __nv_bfloat16 g_A[(size_t)MTOT * KP];   // 50 MB packed x
__device__ __nv_bfloat16 g_Bm[(size_t)HD * KP];    // 393 KB packed W (N-major)
__device__ float g_h1[(size_t)MTOT * HD];          // 134 MB
__device__ float g_out1[(size_t)MTOT * HD];        // 134 MB
__device__ float g_z[Bsz * Nn];

__device__ __forceinline__ uint32_t smem_u32(const void* p) {
    uint32_t a;
    asm("{ .reg .u64 t; cvta.to.shared.u64 t, %1; cvt.u32.u64 %0, t; }" : "=r"(a) : "l"(p));
    return a;
}

// ============================================================================
// conversion kernels: fp32 -> packed split-bf16
// ============================================================================
__global__ void __launch_bounds__(256) conv_x(const float* __restrict__ x) {
    int idx = blockIdx.x * 256 + threadIdx.x;      // 2,097,152 float4 units
    int m = idx >> 5, j4 = (idx & 31) << 2;
    float4 v = *(const float4*)(x + (size_t)m * 128 + j4);
    __nv_bfloat16 h[4], l[4];
    float vv[4] = {v.x, v.y, v.z, v.w};
#pragma unroll
    for (int i = 0; i < 4; ++i) {
        h[i] = __float2bfloat16_rn(vv[i]);
        l[i] = __float2bfloat16_rn(vv[i] - __bfloat162float(h[i]));
    }
    __nv_bfloat16* dst = g_A + (size_t)m * KP + j4;
    *(uint2*)(dst)       = *(uint2*)h;
    *(uint2*)(dst + 128) = *(uint2*)h;
    *(uint2*)(dst + 256) = *(uint2*)l;
}
__global__ void __launch_bounds__(128) conv_w(const float* __restrict__ W1) {
    int n = blockIdx.x, k = threadIdx.x;
    float w = W1[(size_t)k * HD + n];
    __nv_bfloat16 hi = __float2bfloat16_rn(w);
    __nv_bfloat16 lo = __float2bfloat16_rn(w - __bfloat162float(hi));
    __nv_bfloat16* dst = g_Bm + (size_t)n * KP;
    dst[k] = hi; dst[128 + k] = lo; dst[256 + k] = hi;
}

// ============================================================================
// K1: HMMA GEMM. C[65536,512] = A[65536,384] x B[512,384]^T (both K-major).
// CTA tile 128x128, 8 warps (2M x 4N), warp tile 64x32, BK=64 double-buffered.
// smem row = 64 bf16 = 128 B; 16B-chunk xor swizzle: chunk' = chunk ^ (row&7).
// ============================================================================
#define BK 64
#define NCHUNK 6          // 384/64
#define ABUF 16384        // 128*128 bytes per buffer

__device__ __forceinline__ void cpa16(uint32_t dst, const void* src) {
    asm volatile("cp.async.cg.shared.global [%0], [%1], 16;" :: "r"(dst), "l"(src));
}
__device__ __forceinline__ void load_chunk(uint32_t sA, uint32_t sB,
                                           const __nv_bfloat16* gA, const __nv_bfloat16* gB,
                                           int kc, int tid) {
    int r = tid >> 1, half = tid & 1;
    const __nv_bfloat16* ga = gA + (size_t)r * KP + kc * BK + half * 32;
    const __nv_bfloat16* gb = gB + (size_t)r * KP + kc * BK + half * 32;
    uint32_t rowoff = (uint32_t)r << 7;
    int sx = r & 7;
#pragma unroll
    for (int i = 0; i < 4; ++i) {
        int c = half * 4 + i;
        uint32_t sw = rowoff + ((uint32_t)(c ^ sx) << 4);
        cpa16(sA + sw, ga + i * 8);
        cpa16(sB + sw, gb + i * 8);
    }
    asm volatile("cp.async.commit_group;" ::: "memory");
}

__global__ void __launch_bounds__(256, 2) gemm_k1() {
    extern __shared__ char dyn[];
    const int tid = threadIdx.x;
    const int wid = tid >> 5, lane = tid & 31;
    const int wm = wid & 1, wn = wid >> 1;          // 2 x 4 warp grid
    const int mt = blockIdx.x >> 2, nt = blockIdx.x & 3;
    const int m0 = mt << 7, n0 = nt << 7;

    uint32_t sb = smem_u32(dyn);
    const __nv_bfloat16* gA = g_A + (size_t)m0 * KP;
    const __nv_bfloat16* gB = g_Bm + (size_t)n0 * KP;

    float acc[4][4][4];
#pragma unroll
    for (int i = 0; i < 4; ++i)
#pragma unroll
        for (int j = 0; j < 4; ++j)
#pragma unroll
            for (int k = 0; k < 4; ++k) acc[i][j][k] = 0.f;

    const int arow = wm * 64 + (lane & 15);
    const int brow = wn * 32 + (lane & 15);
    const int cs = lane >> 4;
    const int asx = arow & 7, bsx = brow & 7;

    load_chunk(sb, sb + 2 * ABUF, gA, gB, 0, tid);

    int buf = 0;
    for (int kc = 0; kc < NCHUNK; ++kc) {
        if (kc < NCHUNK - 1)
            load_chunk(sb + (buf ^ 1) * ABUF, sb + 2 * ABUF + (buf ^ 1) * ABUF, gA, gB, kc + 1, tid);
        if (kc < NCHUNK - 1) asm volatile("cp.async.wait_group 1;" ::: "memory");
        else                 asm volatile("cp.async.wait_group 0;" ::: "memory");
        __syncthreads();

        uint32_t Ab = sb + buf * ABUF;
        uint32_t Bb = sb + 2 * ABUF + buf * ABUF;
#pragma unroll
        for (int ks = 0; ks < 4; ++ks) {
            uint32_t a[4][4], bfr[4][2];
#pragma unroll
            for (int ti = 0; ti < 4; ++ti) {
                uint32_t addr = Ab + ((uint32_t)(arow + ti * 16) << 7)
                              + ((uint32_t)((ks * 2 + cs) ^ asx) << 4);
                asm volatile("ldmatrix.sync.aligned.m8n8.x4.shared.b16 {%0,%1,%2,%3}, [%4];"
                    : "=r"(a[ti][0]), "=r"(a[ti][1]), "=r"(a[ti][2]), "=r"(a[ti][3]) : "r"(addr));
            }
#pragma unroll
            for (int tjp = 0; tjp < 2; ++tjp) {
                uint32_t q0, q1, q2, q3;
                uint32_t addr = Bb + ((uint32_t)(brow + tjp * 16) << 7)
                              + ((uint32_t)((ks * 2 + cs) ^ bsx) << 4);
                asm volatile("ldmatrix.sync.aligned.m8n8.x4.shared.b16 {%0,%1,%2,%3}, [%4];"
                    : "=r"(q0), "=r"(q1), "=r"(q2), "=r"(q3) : "r"(addr));
                bfr[tjp * 2][0] = q0;     bfr[tjp * 2][1] = q2;
                bfr[tjp * 2 + 1][0] = q1; bfr[tjp * 2 + 1][1] = q3;
            }
#pragma unroll
            for (int ti = 0; ti < 4; ++ti)
#pragma unroll
                for (int tj = 0; tj < 4; ++tj)
                    asm volatile(
                        "mma.sync.aligned.m16n8k16.row.col.f32.bf16.bf16.f32 "
                        "{%0,%1,%2,%3}, {%4,%5,%6,%7}, {%8,%9}, {%0,%1,%2,%3};"
                        : "+f"(acc[ti][tj][0]), "+f"(acc[ti][tj][1]),
                          "+f"(acc[ti][tj][2]), "+f"(acc[ti][tj][3])
                        : "r"(a[ti][0]), "r"(a[ti][1]), "r"(a[ti][2]), "r"(a[ti][3]),
                          "r"(bfr[tj][0]), "r"(bfr[tj][1]));
        }
        __syncthreads();
        buf ^= 1;
    }

    // epilogue: c0,c1 -> (row q, col p2..p2+1); c2,c3 -> row q+8
    const int q = lane >> 2, p2 = (lane & 3) << 1;
#pragma unroll
    for (int ti = 0; ti < 4; ++ti) {
        int m = m0 + wm * 64 + ti * 16 + q;
#pragma unroll
        for (int tj = 0; tj < 4; ++tj) {
            int n = n0 + wn * 32 + tj * 8 + p2;
            *(float2*)(g_h1 + (size_t)m * HD + n)       = make_float2(acc[ti][tj][0], acc[ti][tj][1]);
            *(float2*)(g_h1 + (size_t)(m + 8) * HD + n) = make_float2(acc[ti][tj][2], acc[ti][tj][3]);
        }
    }
}

// ============================================================================
// K2: layer-1 attention, threshold sweep
// ============================================================================
__device__ __forceinline__ unsigned f2u_ord(float f) {
    unsigned u = __float_as_uint(f);
    return (u & 0x80000000u) ? ~u : (u | 0x80000000u);
}
#define HSTRIDE 132

__global__ void __launch_bounds__(256) gat1_attn(const float* __restrict__ att_src,
                                                 const float* __restrict__ att_dst) {
    const int b  = blockIdx.x >> 2;
    const int hh = blockIdx.x & 3;
    const int tid = threadIdx.x;

    extern __shared__ float sm[];
    float* hsm = sm;
    float* pv  = hsm + 256 * HSTRIDE;
    float* qv  = pv + 256;
    float* e1  = qv + 256;
    float* e2  = e1 + 256;
    float* asv = e2 + 256;
    float* adv = asv + 256;
    unsigned* keys = (unsigned*)(adv + 256);
    unsigned* payl = keys + 512;
    float* srcv = (float*)(payl + 512);
    float* dstv = srcv + 128;

    if (tid < 128) {
        srcv[tid] = att_src[hh * 128 + tid];
        dstv[tid] = att_dst[hh * 128 + tid];
    }

    const float* hbase = g_h1 + ((size_t)(b * 256) * 4 + hh) * 128;
    for (int idx = tid; idx < 256 * 32; idx += 256) {
        int j = idx >> 5, d4 = (idx & 31) << 2;
        *(float4*)(hsm + j * HSTRIDE + d4) = *(const float4*)(hbase + (size_t)j * 512 + d4);
    }
    __syncthreads();

    {
        int w = tid >> 5, lane = tid & 31;
        for (int r = 0; r < 32; ++r) {
            int j = (w << 5) + r;
            float s1 = 0.f, s2 = 0.f;
#pragma unroll
            for (int u = 0; u < 4; ++u) {
                float hv = hsm[j * HSTRIDE + (u << 5) + lane];
                s1 = fmaf(hv, srcv[(u << 5) + lane], s1);
                s2 = fmaf(hv, dstv[(u << 5) + lane], s2);
            }
#pragma unroll
            for (int o = 16; o > 0; o >>= 1) {
                s1 += __shfl_down_sync(0xFFFFFFFFu, s1, o);
                s2 += __shfl_down_sync(0xFFFFFFFFu, s2, o);
            }
            if (lane == 0) { asv[j] = s1; adv[j] = s2; }
        }
    }
    __syncthreads();

    {
        float a = asv[tid], d = adv[tid];
        pv[tid] = expf(a);        qv[tid] = expf(0.2f * a);
        e1[tid] = expf(d);        e2[tid] = expf(0.2f * d);
        keys[tid]       = f2u_ord(a);   payl[tid]       = (unsigned)tid;
        keys[256 + tid] = f2u_ord(-d);  payl[256 + tid] = (unsigned)(256 + tid);
    }

    for (unsigned k = 2; k <= 512; k <<= 1)
        for (unsigned j = k >> 1; j > 0; j >>= 1) {
            __syncthreads();
            for (int i = tid; i < 512; i += 256) {
                int ixj = i ^ (int)j;
                if (ixj > i) {
                    unsigned ka = keys[i], kb = keys[ixj];
                    bool up = ((i & (int)k) == 0);
                    if ((ka > kb) == up) {
                        keys[i] = kb; keys[ixj] = ka;
                        unsigned t = payl[i]; payl[i] = payl[ixj]; payl[ixj] = t;
                    }
                }
            }
        }
    __syncthreads();

    if (tid < 128) {
        float sp0 = 0.f, sp1 = 0.f, sp2 = 0.f, sp3 = 0.f;
        float ps0 = 0.f, ps1 = 0.f, ps2 = 0.f, ps3 = 0.f;
        for (int j = 0; j < 256; j += 4) {
            float p0 = pv[j], p1 = pv[j + 1], p2 = pv[j + 2], p3 = pv[j + 3];
            sp0 = fmaf(p0, hsm[(j + 0) * HSTRIDE + tid], sp0);
            sp1 = fmaf(p1, hsm[(j + 1) * HSTRIDE + tid], sp1);
            sp2 = fmaf(p2, hsm[(j + 2) * HSTRIDE + tid], sp2);
            sp3 = fmaf(p3, hsm[(j + 3) * HSTRIDE + tid], sp3);
            ps0 += p0; ps1 += p1; ps2 += p2; ps3 += p3;
        }
        float Sp = (sp0 + sp1) + (sp2 + sp3);
        float Ps = (ps0 + ps1) + (ps2 + ps3);
        float Sn = 0.f, Qs = 0.f;
        float* ob = g_out1 + ((size_t)(b * 256) * 4 + hh) * 128 + tid;
        for (int e = 0; e < 512; ++e) {
            unsigned pl = payl[e];
            if (pl < 256) {
                float pj = pv[pl], qj = qv[pl];
                float hv = hsm[pl * HSTRIDE + tid];
                Sp = fmaf(-pj, hv, Sp);
                Sn = fmaf(qj, hv, Sn);
                Ps -= pj; Qs += qj;
            } else {
                int i = (int)pl - 256;
                float c1 = e1[i], c2 = e2[i];
                float num = fmaf(c1, Sp, c2 * Sn);
                float den = fmaf(c1, Ps, c2 * Qs);
                ob[(size_t)i * 512] = num / den;
            }
        }
    }
}

// ============================================================================
// K3: LayerNorm + ELU + dot W2
// ============================================================================
__global__ void __launch_bounds__(128) ln_elu_z_kernel(const float* __restrict__ b1,
                                                       const float* __restrict__ gamma,
                                                       const float* __restrict__ beta,
                                                       const float* __restrict__ W2) {
    const int row = blockIdx.x;
    const int tid = threadIdx.x;
    const int lane = tid & 31, w = tid >> 5;
    __shared__ float red[16];

    const float* r = g_out1 + (size_t)row * 512;
    float4 v  = *(const float4*)(r + (tid << 2));
    float4 bb = *(const float4*)(b1 + (tid << 2));
    v.x += bb.x; v.y += bb.y; v.z += bb.z; v.w += bb.w;

    float s  = v.x + v.y + v.z + v.w;
    float sq = v.x * v.x + v.y * v.y + v.z * v.z + v.w * v.w;
#pragma unroll
    for (int o = 16; o > 0; o >>= 1) {
        s  += __shfl_down_sync(0xFFFFFFFFu, s, o);
        sq += __shfl_down_sync(0xFFFFFFFFu, sq, o);
    }
    if (!lane) { red[w] = s; red[8 + w] = sq; }
    __syncthreads();
    float st  = red[0] + red[1] + red[2] + red[3];
    float sqt = red[8] + red[9] + red[10] + red[11];
    float mu   = st * (1.0f / 512.0f);
    float var  = sqt * (1.0f / 512.0f) - mu * mu;
    float rstd = rsqrtf(var + 1e-5f);

    float4 g4 = *(const float4*)(gamma + (tid << 2));
    float4 be = *(const float4*)(beta + (tid << 2));
    float4 w4 = *(const float4*)(W2 + (tid << 2));

    float y0 = (v.x - mu) * rstd * g4.x + be.x; y0 = y0 > 0.f ? y0 : expm1f(y0);
    float y1 = (v.y - mu) * rstd * g4.y + be.y; y1 = y1 > 0.f ? y1 : expm1f(y1);
    float y2 = (v.z - mu) * rstd * g4.z + be.z; y2 = y2 > 0.f ? y2 : expm1f(y2);
    float y3 = (v.w - mu) * rstd * g4.w + be.w; y3 = y3 > 0.f ? y3 : expm1f(y3);

    float acc = y0 * w4.x + y1 * w4.y + y2 * w4.z + y3 * w4.w;
#pragma unroll
    for (int o = 16; o > 0; o >>= 1) acc += __shfl_down_sync(0xFFFFFFFFu, acc, o);
    __syncthreads();
    if (!lane) red[w] = acc;
    __syncthreads();
    if (!tid) g_z[row] = red[0] + red[1] + red[2] + red[3];
}

// ============================================================================
// K4: layer-2 scalar attention
// ============================================================================
__global__ void __launch_bounds__(256) gat2_attn_kernel(const float* __restrict__ s_src,
                                                        const float* __restrict__ s_dst,
                                                        const float* __restrict__ b2,
                                                        float* __restrict__ out) {
    const int b = blockIdx.x;
    const int tid = threadIdx.x;
    __shared__ float zs[256], asx[256];
    float zv = g_z[b * 256 + tid];
    float ssc = s_src[0], sdc = s_dst[0];
    zs[tid] = zv;
    asx[tid] = zv * ssc;
    __syncthreads();
    float adi = zv * sdc;
    float num = 0.f, den = 0.f;
    for (int j = 0; j < 256; ++j) {
        float e = adi + asx[j];
        e = e > 0.f ? e : 0.2f * e;
        float wgt = expf(e);
        num = fmaf(wgt, zs[j], num);
        den += wgt;
    }
    out[b * 256 + tid] = num / den + b2[0];
}

// ============================================================================
// launch
// ============================================================================
extern "C" void kernel_launch(void* const* d_in, const int* in_sizes, int n_in,
                              void* d_out, int out_size) {
    const float* x     = (const float*)d_in[0];
    const float* W1    = (const float*)d_in[2];
    const float* as1   = (const float*)d_in[3];
    const float* ad1   = (const float*)d_in[4];
    const float* b1    = (const float*)d_in[5];
    const float* gamma = (const float*)d_in[6];
    const float* beta  = (const float*)d_in[7];
    const float* W2    = (const float*)d_in[8];
    const float* as2   = (const float*)d_in[9];
    const float* ad2   = (const float*)d_in[10];
    const float* b2    = (const float*)d_in[11];
    float* out = (float*)d_out;

    const int smem_gemm = 4 * ABUF;                                   // 65536
    const int smem_attn = (256 * HSTRIDE + 6 * 256 + 1024 + 256) * 4; // 146432
    cudaFuncSetAttribute(gemm_k1, cudaFuncAttributeMaxDynamicSharedMemorySize, smem_gemm);
    cudaFuncSetAttribute(gat1_attn, cudaFuncAttributeMaxDynamicSharedMemorySize, smem_attn);

    conv_x<<<8192, 256>>>(x);
    conv_w<<<512, 128>>>(W1);
    gemm_k1<<<2048, 256, smem_gemm>>>();
    gat1_attn<<<Bsz * Hh, 256, smem_attn>>>(as1, ad1);
    ln_elu_z_kernel<<<Bsz * Nn, 128>>>(b1, gamma, beta, W2);
    gat2_attn_kernel<<<Bsz, 256>>>(as2, ad2, b2, out);
}

// round 6
// speedup vs baseline: 1.5064x; 1.3252x over previous
#include <cuda_runtime.h>
#include <cuda_bf16.h>
#include <math.h>
#include <stdint.h>

// GAT2: B=256, N=256, DIN=128, H=4, DH=128.
//   conv_x/conv_w: split fp32 -> bf16 hi/lo, packed K=384 (x*W = xh*Wh + xh*Wl + xl*Wh)
//   K1: mma.sync (HMMA) bf16 GEMM 65536x512, K=384, fp32 accum.
//   K2: per-(b,h) attention via rank-by-count + chunked prefix sums (no sort, no serial sweep)
//   K3: LayerNorm + ELU + dot W2 -> z
//   K4: layer-2 scalar attention

#define Bsz 256
#define Nn  256
#define Hh  4
#define HD  512
#define KP  384
#define MTOT 65536

__device__ __nv_bfloat16 g_A[(size_t)MTOT * KP];   // 50 MB packed x
__device__ __nv_bfloat16 g_Bm[(size_t)HD * KP];    // 393 KB packed W (N-major)
__device__ float g_h1[(size_t)MTOT * HD];          // 134 MB
__device__ float g_out1[(size_t)MTOT * HD];        // 134 MB
__device__ float g_z[Bsz * Nn];

__device__ __forceinline__ uint32_t smem_u32(const void* p) {
    uint32_t a;
    asm("{ .reg .u64 t; cvta.to.shared.u64 t, %1; cvt.u32.u64 %0, t; }" : "=r"(a) : "l"(p));
    return a;
}

// ============================================================================
// conversion kernels: fp32 -> packed split-bf16
// ============================================================================
__global__ void __launch_bounds__(256) conv_x(const float* __restrict__ x) {
    int idx = blockIdx.x * 256 + threadIdx.x;
    int m = idx >> 5, j4 = (idx & 31) << 2;
    float4 v = *(const float4*)(x + (size_t)m * 128 + j4);
    __nv_bfloat16 h[4], l[4];
    float vv[4] = {v.x, v.y, v.z, v.w};
#pragma unroll
    for (int i = 0; i < 4; ++i) {
        h[i] = __float2bfloat16_rn(vv[i]);
        l[i] = __float2bfloat16_rn(vv[i] - __bfloat162float(h[i]));
    }
    __nv_bfloat16* dst = g_A + (size_t)m * KP + j4;
    *(uint2*)(dst)       = *(uint2*)h;
    *(uint2*)(dst + 128) = *(uint2*)h;
    *(uint2*)(dst + 256) = *(uint2*)l;
}
__global__ void __launch_bounds__(128) conv_w(const float* __restrict__ W1) {
    int n = blockIdx.x, k = threadIdx.x;
    float w = W1[(size_t)k * HD + n];
    __nv_bfloat16 hi = __float2bfloat16_rn(w);
    __nv_bfloat16 lo = __float2bfloat16_rn(w - __bfloat162float(hi));
    __nv_bfloat16* dst = g_Bm + (size_t)n * KP;
    dst[k] = hi; dst[128 + k] = lo; dst[256 + k] = hi;
}

// ============================================================================
// K1: HMMA GEMM (proven round 4)
// ============================================================================
#define BK 64
#define NCHUNK 6
#define ABUF 16384

__device__ __forceinline__ void cpa16(uint32_t dst, const void* src) {
    asm volatile("cp.async.cg.shared.global [%0], [%1], 16;" :: "r"(dst), "l"(src));
}
__device__ __forceinline__ void load_chunk(uint32_t sA, uint32_t sB,
                                           const __nv_bfloat16* gA, const __nv_bfloat16* gB,
                                           int kc, int tid) {
    int r = tid >> 1, half = tid & 1;
    const __nv_bfloat16* ga = gA + (size_t)r * KP + kc * BK + half * 32;
    const __nv_bfloat16* gb = gB + (size_t)r * KP + kc * BK + half * 32;
    uint32_t rowoff = (uint32_t)r << 7;
    int sx = r & 7;
#pragma unroll
    for (int i = 0; i < 4; ++i) {
        int c = half * 4 + i;
        uint32_t sw = rowoff + ((uint32_t)(c ^ sx) << 4);
        cpa16(sA + sw, ga + i * 8);
        cpa16(sB + sw, gb + i * 8);
    }
    asm volatile("cp.async.commit_group;" ::: "memory");
}

__global__ void __launch_bounds__(256, 2) gemm_k1() {
    extern __shared__ char dyn[];
    const int tid = threadIdx.x;
    const int wid = tid >> 5, lane = tid & 31;
    const int wm = wid & 1, wn = wid >> 1;
    const int mt = blockIdx.x >> 2, nt = blockIdx.x & 3;
    const int m0 = mt << 7, n0 = nt << 7;

    uint32_t sb = smem_u32(dyn);
    const __nv_bfloat16* gA = g_A + (size_t)m0 * KP;
    const __nv_bfloat16* gB = g_Bm + (size_t)n0 * KP;

    float acc[4][4][4];
#pragma unroll
    for (int i = 0; i < 4; ++i)
#pragma unroll
        for (int j = 0; j < 4; ++j)
#pragma unroll
            for (int k = 0; k < 4; ++k) acc[i][j][k] = 0.f;

    const int arow = wm * 64 + (lane & 15);
    const int brow = wn * 32 + (lane & 15);
    const int cs = lane >> 4;
    const int asx = arow & 7, bsx = brow & 7;

    load_chunk(sb, sb + 2 * ABUF, gA, gB, 0, tid);

    int buf = 0;
    for (int kc = 0; kc < NCHUNK; ++kc) {
        if (kc < NCHUNK - 1)
            load_chunk(sb + (buf ^ 1) * ABUF, sb + 2 * ABUF + (buf ^ 1) * ABUF, gA, gB, kc + 1, tid);
        if (kc < NCHUNK - 1) asm volatile("cp.async.wait_group 1;" ::: "memory");
        else                 asm volatile("cp.async.wait_group 0;" ::: "memory");
        __syncthreads();

        uint32_t Ab = sb + buf * ABUF;
        uint32_t Bb = sb + 2 * ABUF + buf * ABUF;
#pragma unroll
        for (int ks = 0; ks < 4; ++ks) {
            uint32_t a[4][4], bfr[4][2];
#pragma unroll
            for (int ti = 0; ti < 4; ++ti) {
                uint32_t addr = Ab + ((uint32_t)(arow + ti * 16) << 7)
                              + ((uint32_t)((ks * 2 + cs) ^ asx) << 4);
                asm volatile("ldmatrix.sync.aligned.m8n8.x4.shared.b16 {%0,%1,%2,%3}, [%4];"
                    : "=r"(a[ti][0]), "=r"(a[ti][1]), "=r"(a[ti][2]), "=r"(a[ti][3]) : "r"(addr));
            }
#pragma unroll
            for (int tjp = 0; tjp < 2; ++tjp) {
                uint32_t q0, q1, q2, q3;
                uint32_t addr = Bb + ((uint32_t)(brow + tjp * 16) << 7)
                              + ((uint32_t)((ks * 2 + cs) ^ bsx) << 4);
                asm volatile("ldmatrix.sync.aligned.m8n8.x4.shared.b16 {%0,%1,%2,%3}, [%4];"
                    : "=r"(q0), "=r"(q1), "=r"(q2), "=r"(q3) : "r"(addr));
                bfr[tjp * 2][0] = q0;     bfr[tjp * 2][1] = q2;
                bfr[tjp * 2 + 1][0] = q1; bfr[tjp * 2 + 1][1] = q3;
            }
#pragma unroll
            for (int ti = 0; ti < 4; ++ti)
#pragma unroll
                for (int tj = 0; tj < 4; ++tj)
                    asm volatile(
                        "mma.sync.aligned.m16n8k16.row.col.f32.bf16.bf16.f32 "
                        "{%0,%1,%2,%3}, {%4,%5,%6,%7}, {%8,%9}, {%0,%1,%2,%3};"
                        : "+f"(acc[ti][tj][0]), "+f"(acc[ti][tj][1]),
                          "+f"(acc[ti][tj][2]), "+f"(acc[ti][tj][3])
                        : "r"(a[ti][0]), "r"(a[ti][1]), "r"(a[ti][2]), "r"(a[ti][3]),
                          "r"(bfr[tj][0]), "r"(bfr[tj][1]));
        }
        __syncthreads();
        buf ^= 1;
    }

    const int q = lane >> 2, p2 = (lane & 3) << 1;
#pragma unroll
    for (int ti = 0; ti < 4; ++ti) {
        int m = m0 + wm * 64 + ti * 16 + q;
#pragma unroll
        for (int tj = 0; tj < 4; ++tj) {
            int n = n0 + wn * 32 + tj * 8 + p2;
            *(float2*)(g_h1 + (size_t)m * HD + n)       = make_float2(acc[ti][tj][0], acc[ti][tj][1]);
            *(float2*)(g_h1 + (size_t)(m + 8) * HD + n) = make_float2(acc[ti][tj][2], acc[ti][tj][3]);
        }
    }
}

// ============================================================================
// K2 v2: rank-by-count + chunk-4 prefix/suffix sums. One block per (b,h).
// ============================================================================
#define HSTRIDE 132
#define NCH 64          // chunks of 4 sorted senders

__global__ void __launch_bounds__(256) gat1_attn(const float* __restrict__ att_src,
                                                 const float* __restrict__ att_dst) {
    const int b  = blockIdx.x >> 2;
    const int hh = blockIdx.x & 3;
    const int tid = threadIdx.x;

    extern __shared__ float sm[];
    float* hsm   = sm;                       // 256*132
    float* sSuf  = hsm + 256 * HSTRIDE;      // 65*128
    float* sPre  = sSuf + 65 * 128;          // 65*128
    float* asv   = sPre + 65 * 128;          // 256
    float* adv   = asv + 256;                // 256
    float* pexp  = adv + 256;                // 256
    float* qexp  = pexp + 256;               // 256
    float* e1    = qexp + 256;               // 256
    float* e2    = e1 + 256;                 // 256
    float* psort = e2 + 256;                 // 256
    float* qsort = psort + 256;              // 256
    int*   sIdx  = (int*)(qsort + 256);      // 256
    int*   kpos  = sIdx + 256;               // 256
    float* rden  = (float*)(kpos + 256);     // 256
    float* srcv  = rden + 256;               // 128
    float* dstv  = srcv + 128;               // 128

    if (tid < 128) {
        srcv[tid] = att_src[hh * 128 + tid];
        dstv[tid] = att_dst[hh * 128 + tid];
    }

    // phase 1: load h tile (256x128) coalesced
    const float* hbase = g_h1 + ((size_t)(b * 256) * 4 + hh) * 128;
#pragma unroll
    for (int i = 0; i < 32; ++i) {
        int idx = tid + (i << 8);
        int j = idx >> 5, d4 = (idx & 31) << 2;
        *(float4*)(hsm + j * HSTRIDE + d4) = *(const float4*)(hbase + (size_t)j * 512 + d4);
    }
    __syncthreads();

    // phase 2: per-thread dots (thread j owns row j) + exps
    {
        const int j = tid;
        float s1 = 0.f, s2 = 0.f;
#pragma unroll
        for (int k4 = 0; k4 < 128; k4 += 4) {
            float4 hv = *(const float4*)(hsm + j * HSTRIDE + k4);
            float4 sv = *(const float4*)(srcv + k4);
            float4 dv = *(const float4*)(dstv + k4);
            s1 = fmaf(hv.x, sv.x, fmaf(hv.y, sv.y, fmaf(hv.z, sv.z, fmaf(hv.w, sv.w, s1))));
            s2 = fmaf(hv.x, dv.x, fmaf(hv.y, dv.y, fmaf(hv.z, dv.z, fmaf(hv.w, dv.w, s2))));
        }
        asv[j] = s1; adv[j] = s2;
        pexp[j] = expf(s1);        qexp[j] = expf(0.2f * s1);
        e1[j]   = expf(s2);        e2[j]   = expf(0.2f * s2);
    }
    __syncthreads();

    // phase 3: rank by counting, split kpos, exact denominator (broadcast loads)
    {
        const int j = tid;
        const float aj = asv[j];
        const float th = -adv[j];
        int rank = 0, k = 0;
        float Sp = 0.f, Sq = 0.f;
        for (int t = 0; t < 256; ++t) {
            float at = asv[t];
            rank += (at < aj) || (at == aj && t < j);
            bool le = (at <= th);
            k += le;
            Sp += le ? 0.f : pexp[t];
            Sq += le ? qexp[t] : 0.f;
        }
        sIdx[rank] = j;
        psort[rank] = pexp[j];
        qsort[rank] = qexp[j];
        kpos[j] = k;
        rden[j] = 1.0f / fmaf(e1[j], Sp, e2[j] * Sq);
    }
    __syncthreads();

    // phase 4: chunk sums (64 chunks of 4 sorted senders) x 128 dims
#pragma unroll
    for (int it = 0; it < 32; ++it) {
        int idx = tid + (it << 8);
        int c = idx >> 7, d = idx & 127;
        float sp = 0.f, sq = 0.f;
#pragma unroll
        for (int u = 0; u < 4; ++u) {
            int t = (c << 2) + u;
            float hv = hsm[sIdx[t] * HSTRIDE + d];
            sp = fmaf(psort[t], hv, sp);
            sq = fmaf(qsort[t], hv, sq);
        }
        sSuf[c * 128 + d] = sp;
        sPre[c * 128 + d] = sq;
    }
    __syncthreads();

    // phase 5: in-place scans over chunks (threads 0-127: suffix P; 128-255: prefix Q)
    {
        int d = tid & 127;
        if (tid < 128) {
            float val = 0.f;
            sSuf[NCH * 128 + d] = 0.f;
            for (int c = NCH - 1; c >= 0; --c) {
                val += sSuf[c * 128 + d];
                sSuf[c * 128 + d] = val;
            }
        } else {
            float val = 0.f;
            for (int c = 0; c < NCH; ++c) {
                float t = sPre[c * 128 + d];
                sPre[c * 128 + d] = val;
                val += t;
            }
            sPre[NCH * 128 + d] = val;
        }
    }
    __syncthreads();

    // phase 6: outputs. group g handles receivers g*128..g*128+127, thread owns dim d.
    {
        const int g = tid >> 7, d = tid & 127;
        float* ob = g_out1 + ((size_t)(b * 256) * 4 + hh) * 128 + d;
        for (int ii = 0; ii < 128; ++ii) {
            int i = (g << 7) + ii;
            int k = kpos[i];
            int c = k >> 2;
            float suf = sSuf[c * 128 + d];
            float pre = sPre[c * 128 + d];
            for (int t = (c << 2); t < k; ++t) {
                float hv = hsm[sIdx[t] * HSTRIDE + d];
                suf = fmaf(-psort[t], hv, suf);
                pre = fmaf(qsort[t], hv, pre);
            }
            float num = fmaf(e1[i], suf, e2[i] * pre);
            ob[(size_t)i * 512] = num * rden[i];
        }
    }
}

// ============================================================================
// K3: LayerNorm + ELU + dot W2
// ============================================================================
__global__ void __launch_bounds__(128) ln_elu_z_kernel(const float* __restrict__ b1,
                                                       const float* __restrict__ gamma,
                                                       const float* __restrict__ beta,
                                                       const float* __restrict__ W2) {
    const int row = blockIdx.x;
    const int tid = threadIdx.x;
    const int lane = tid & 31, w = tid >> 5;
    __shared__ float red[16];

    const float* r = g_out1 + (size_t)row * 512;
    float4 v  = *(const float4*)(r + (tid << 2));
    float4 bb = *(const float4*)(b1 + (tid << 2));
    v.x += bb.x; v.y += bb.y; v.z += bb.z; v.w += bb.w;

    float s  = v.x + v.y + v.z + v.w;
    float sq = v.x * v.x + v.y * v.y + v.z * v.z + v.w * v.w;
#pragma unroll
    for (int o = 16; o > 0; o >>= 1) {
        s  += __shfl_down_sync(0xFFFFFFFFu, s, o);
        sq += __shfl_down_sync(0xFFFFFFFFu, sq, o);
    }
    if (!lane) { red[w] = s; red[8 + w] = sq; }
    __syncthreads();
    float st  = red[0] + red[1] + red[2] + red[3];
    float sqt = red[8] + red[9] + red[10] + red[11];
    float mu   = st * (1.0f / 512.0f);
    float var  = sqt * (1.0f / 512.0f) - mu * mu;
    float rstd = rsqrtf(var + 1e-5f);

    float4 g4 = *(const float4*)(gamma + (tid << 2));
    float4 be = *(const float4*)(beta + (tid << 2));
    float4 w4 = *(const float4*)(W2 + (tid << 2));

    float y0 = (v.x - mu) * rstd * g4.x + be.x; y0 = y0 > 0.f ? y0 : expm1f(y0);
    float y1 = (v.y - mu) * rstd * g4.y + be.y; y1 = y1 > 0.f ? y1 : expm1f(y1);
    float y2 = (v.z - mu) * rstd * g4.z + be.z; y2 = y2 > 0.f ? y2 : expm1f(y2);
    float y3 = (v.w - mu) * rstd * g4.w + be.w; y3 = y3 > 0.f ? y3 : expm1f(y3);

    float acc = y0 * w4.x + y1 * w4.y + y2 * w4.z + y3 * w4.w;
#pragma unroll
    for (int o = 16; o > 0; o >>= 1) acc += __shfl_down_sync(0xFFFFFFFFu, acc, o);
    __syncthreads();
    if (!lane) red[w] = acc;
    __syncthreads();
    if (!tid) g_z[row] = red[0] + red[1] + red[2] + red[3];
}

// ============================================================================
// K4: layer-2 scalar attention
// ============================================================================
__global__ void __launch_bounds__(256) gat2_attn_kernel(const float* __restrict__ s_src,
                                                        const float* __restrict__ s_dst,
                                                        const float* __restrict__ b2,
                                                        float* __restrict__ out) {
    const int b = blockIdx.x;
    const int tid = threadIdx.x;
    __shared__ float zs[256], asx[256];
    float zv = g_z[b * 256 + tid];
    float ssc = s_src[0], sdc = s_dst[0];
    zs[tid] = zv;
    asx[tid] = zv * ssc;
    __syncthreads();
    float adi = zv * sdc;
    float num = 0.f, den = 0.f;
    for (int j = 0; j < 256; ++j) {
        float e = adi + asx[j];
        e = e > 0.f ? e : 0.2f * e;
        float wgt = expf(e);
        num = fmaf(wgt, zs[j], num);
        den += wgt;
    }
    out[b * 256 + tid] = num / den + b2[0];
}

// ============================================================================
// launch
// ============================================================================
extern "C" void kernel_launch(void* const* d_in, const int* in_sizes, int n_in,
                              void* d_out, int out_size) {
    const float* x     = (const float*)d_in[0];
    const float* W1    = (const float*)d_in[2];
    const float* as1   = (const float*)d_in[3];
    const float* ad1   = (const float*)d_in[4];
    const float* b1    = (const float*)d_in[5];
    const float* gamma = (const float*)d_in[6];
    const float* beta  = (const float*)d_in[7];
    const float* W2    = (const float*)d_in[8];
    const float* as2   = (const float*)d_in[9];
    const float* ad2   = (const float*)d_in[10];
    const float* b2    = (const float*)d_in[11];
    float* out = (float*)d_out;

    const int smem_gemm = 4 * ABUF;                                   // 65536
    const int smem_attn = (256 * HSTRIDE + 2 * 65 * 128 + 11 * 256 + 2 * 128) * 4; // 214016
    cudaFuncSetAttribute(gemm_k1, cudaFuncAttributeMaxDynamicSharedMemorySize, smem_gemm);
    cudaFuncSetAttribute(gat1_attn, cudaFuncAttributeMaxDynamicSharedMemorySize, smem_attn);

    conv_x<<<8192, 256>>>(x);
    conv_w<<<512, 128>>>(W1);
    gemm_k1<<<2048, 256, smem_gemm>>>();
    gat1_attn<<<Bsz * Hh, 256, smem_attn>>>(as1, ad1);
    ln_elu_z_kernel<<<Bsz * Nn, 128>>>(b1, gamma, beta, W2);
    gat2_attn_kernel<<<Bsz, 256>>>(as2, ad2, b2, out);
}

// round 7
// speedup vs baseline: 1.7560x; 1.1656x over previous
#include <cuda_runtime.h>
#include <cuda_bf16.h>
#include <math.h>
#include <stdint.h>

// GAT2: B=256, N=256, DIN=128, H=4, DH=128.
//   conv_x/conv_w: split fp32 -> bf16 hi/lo, packed K=384 (x*W = xh*Wh + xh*Wl + xl*Wh)
//   K1 : mma.sync (HMMA) bf16 GEMM 65536x512, K=384, fp32 accum.
//   K2a: per-(b,h) scalars: as/ad dots, exps, rank-by-count, kpos, exact denominator
//   K2b: per-(b,h,dim-half) aggregation via chunk-4 prefix/suffix sums
//   K3 : LayerNorm + ELU + dot W2 -> z
//   K4 : layer-2 scalar attention

#define Bsz 256
#define Nn  256
#define Hh  4
#define HD  512
#define KP  384
#define MTOT 65536

__device__ __nv_bfloat16 g_A[(size_t)MTOT * KP];   // 50 MB packed x
__device__ __nv_bfloat16 g_Bm[(size_t)HD * KP];    // 393 KB packed W (N-major)
__device__ float g_h1[(size_t)MTOT * HD];          // 134 MB
__device__ float g_out1[(size_t)MTOT * HD];        // 134 MB
__device__ float g_z[Bsz * Nn];

// K2 scalar interchange arrays (per (b,h): 256 entries)
__device__ int   g_sidx[Bsz * Hh * 256];
__device__ float g_psort[Bsz * Hh * 256];
__device__ float g_qsort[Bsz * Hh * 256];
__device__ int   g_kpos[Bsz * Hh * 256];
__device__ float g_rden[Bsz * Hh * 256];
__device__ float g_e1[Bsz * Hh * 256];
__device__ float g_e2[Bsz * Hh * 256];

__device__ __forceinline__ uint32_t smem_u32(const void* p) {
    uint32_t a;
    asm("{ .reg .u64 t; cvta.to.shared.u64 t, %1; cvt.u32.u64 %0, t; }" : "=r"(a) : "l"(p));
    return a;
}

// ============================================================================
// conversion kernels: fp32 -> packed split-bf16
// ============================================================================
__global__ void __launch_bounds__(256) conv_x(const float* __restrict__ x) {
    int idx = blockIdx.x * 256 + threadIdx.x;
    int m = idx >> 5, j4 = (idx & 31) << 2;
    float4 v = *(const float4*)(x + (size_t)m * 128 + j4);
    __nv_bfloat16 h[4], l[4];
    float vv[4] = {v.x, v.y, v.z, v.w};
#pragma unroll
    for (int i = 0; i < 4; ++i) {
        h[i] = __float2bfloat16_rn(vv[i]);
        l[i] = __float2bfloat16_rn(vv[i] - __bfloat162float(h[i]));
    }
    __nv_bfloat16* dst = g_A + (size_t)m * KP + j4;
    *(uint2*)(dst)       = *(uint2*)h;
    *(uint2*)(dst + 128) = *(uint2*)h;
    *(uint2*)(dst + 256) = *(uint2*)l;
}
__global__ void __launch_bounds__(128) conv_w(const float* __restrict__ W1) {
    int n = blockIdx.x, k = threadIdx.x;
    float w = W1[(size_t)k * HD + n];
    __nv_bfloat16 hi = __float2bfloat16_rn(w);
    __nv_bfloat16 lo = __float2bfloat16_rn(w - __bfloat162float(hi));
    __nv_bfloat16* dst = g_Bm + (size_t)n * KP;
    dst[k] = hi; dst[128 + k] = lo; dst[256 + k] = hi;
}

// ============================================================================
// K1: HMMA GEMM (proven round 4)
// ============================================================================
#define BK 64
#define NCHUNK 6
#define ABUF 16384

__device__ __forceinline__ void cpa16(uint32_t dst, const void* src) {
    asm volatile("cp.async.cg.shared.global [%0], [%1], 16;" :: "r"(dst), "l"(src));
}
__device__ __forceinline__ void load_chunk(uint32_t sA, uint32_t sB,
                                           const __nv_bfloat16* gA, const __nv_bfloat16* gB,
                                           int kc, int tid) {
    int r = tid >> 1, half = tid & 1;
    const __nv_bfloat16* ga = gA + (size_t)r * KP + kc * BK + half * 32;
    const __nv_bfloat16* gb = gB + (size_t)r * KP + kc * BK + half * 32;
    uint32_t rowoff = (uint32_t)r << 7;
    int sx = r & 7;
#pragma unroll
    for (int i = 0; i < 4; ++i) {
        int c = half * 4 + i;
        uint32_t sw = rowoff + ((uint32_t)(c ^ sx) << 4);
        cpa16(sA + sw, ga + i * 8);
        cpa16(sB + sw, gb + i * 8);
    }
    asm volatile("cp.async.commit_group;" ::: "memory");
}

__global__ void __launch_bounds__(256, 2) gemm_k1() {
    extern __shared__ char dyn[];
    const int tid = threadIdx.x;
    const int wid = tid >> 5, lane = tid & 31;
    const int wm = wid & 1, wn = wid >> 1;
    const int mt = blockIdx.x >> 2, nt = blockIdx.x & 3;
    const int m0 = mt << 7, n0 = nt << 7;

    uint32_t sb = smem_u32(dyn);
    const __nv_bfloat16* gA = g_A + (size_t)m0 * KP;
    const __nv_bfloat16* gB = g_Bm + (size_t)n0 * KP;

    float acc[4][4][4];
#pragma unroll
    for (int i = 0; i < 4; ++i)
#pragma unroll
        for (int j = 0; j < 4; ++j)
#pragma unroll
            for (int k = 0; k < 4; ++k) acc[i][j][k] = 0.f;

    const int arow = wm * 64 + (lane & 15);
    const int brow = wn * 32 + (lane & 15);
    const int cs = lane >> 4;
    const int asx = arow & 7, bsx = brow & 7;

    load_chunk(sb, sb + 2 * ABUF, gA, gB, 0, tid);

    int buf = 0;
    for (int kc = 0; kc < NCHUNK; ++kc) {
        if (kc < NCHUNK - 1)
            load_chunk(sb + (buf ^ 1) * ABUF, sb + 2 * ABUF + (buf ^ 1) * ABUF, gA, gB, kc + 1, tid);
        if (kc < NCHUNK - 1) asm volatile("cp.async.wait_group 1;" ::: "memory");
        else                 asm volatile("cp.async.wait_group 0;" ::: "memory");
        __syncthreads();

        uint32_t Ab = sb + buf * ABUF;
        uint32_t Bb = sb + 2 * ABUF + buf * ABUF;
#pragma unroll
        for (int ks = 0; ks < 4; ++ks) {
            uint32_t a[4][4], bfr[4][2];
#pragma unroll
            for (int ti = 0; ti < 4; ++ti) {
                uint32_t addr = Ab + ((uint32_t)(arow + ti * 16) << 7)
                              + ((uint32_t)((ks * 2 + cs) ^ asx) << 4);
                asm volatile("ldmatrix.sync.aligned.m8n8.x4.shared.b16 {%0,%1,%2,%3}, [%4];"
                    : "=r"(a[ti][0]), "=r"(a[ti][1]), "=r"(a[ti][2]), "=r"(a[ti][3]) : "r"(addr));
            }
#pragma unroll
            for (int tjp = 0; tjp < 2; ++tjp) {
                uint32_t q0, q1, q2, q3;
                uint32_t addr = Bb + ((uint32_t)(brow + tjp * 16) << 7)
                              + ((uint32_t)((ks * 2 + cs) ^ bsx) << 4);
                asm volatile("ldmatrix.sync.aligned.m8n8.x4.shared.b16 {%0,%1,%2,%3}, [%4];"
                    : "=r"(q0), "=r"(q1), "=r"(q2), "=r"(q3) : "r"(addr));
                bfr[tjp * 2][0] = q0;     bfr[tjp * 2][1] = q2;
                bfr[tjp * 2 + 1][0] = q1; bfr[tjp * 2 + 1][1] = q3;
            }
#pragma unroll
            for (int ti = 0; ti < 4; ++ti)
#pragma unroll
                for (int tj = 0; tj < 4; ++tj)
                    asm volatile(
                        "mma.sync.aligned.m16n8k16.row.col.f32.bf16.bf16.f32 "
                        "{%0,%1,%2,%3}, {%4,%5,%6,%7}, {%8,%9}, {%0,%1,%2,%3};"
                        : "+f"(acc[ti][tj][0]), "+f"(acc[ti][tj][1]),
                          "+f"(acc[ti][tj][2]), "+f"(acc[ti][tj][3])
                        : "r"(a[ti][0]), "r"(a[ti][1]), "r"(a[ti][2]), "r"(a[ti][3]),
                          "r"(bfr[tj][0]), "r"(bfr[tj][1]));
        }
        __syncthreads();
        buf ^= 1;
    }

    const int q = lane >> 2, p2 = (lane & 3) << 1;
#pragma unroll
    for (int ti = 0; ti < 4; ++ti) {
        int m = m0 + wm * 64 + ti * 16 + q;
#pragma unroll
        for (int tj = 0; tj < 4; ++tj) {
            int n = n0 + wn * 32 + tj * 8 + p2;
            *(float2*)(g_h1 + (size_t)m * HD + n)       = make_float2(acc[ti][tj][0], acc[ti][tj][1]);
            *(float2*)(g_h1 + (size_t)(m + 8) * HD + n) = make_float2(acc[ti][tj][2], acc[ti][tj][3]);
        }
    }
}

// ============================================================================
// K2a: per-(b,h) scalars. 1024 blocks x 256 threads, ~5 KB smem (high occ).
// Warp-per-row GEMV from gmem (coalesced), exps, rank-by-count, kpos, 1/den.
// ============================================================================
__global__ void __launch_bounds__(256) gat1_scalars(const float* __restrict__ att_src,
                                                    const float* __restrict__ att_dst) {
    const int bh = blockIdx.x;              // b*4+hh
    const int b = bh >> 2, hh = bh & 3;
    const int tid = threadIdx.x;
    const int wid = tid >> 5, lane = tid & 31;

    __shared__ float srcv[128], dstv[128];
    __shared__ float asv[256], adv[256], pexp[256], qexp[256];

    if (tid < 128) {
        srcv[tid] = att_src[hh * 128 + tid];
        dstv[tid] = att_dst[hh * 128 + tid];
    }
    __syncthreads();

    const float* hbase = g_h1 + (size_t)(b * 256) * 512 + hh * 128;
    for (int r = wid; r < 256; r += 8) {
        const float* row = hbase + (size_t)r * 512;
        float s1 = 0.f, s2 = 0.f;
#pragma unroll
        for (int u = 0; u < 4; ++u) {
            float hv = row[u * 32 + lane];
            s1 = fmaf(hv, srcv[u * 32 + lane], s1);
            s2 = fmaf(hv, dstv[u * 32 + lane], s2);
        }
#pragma unroll
        for (int o = 16; o > 0; o >>= 1) {
            s1 += __shfl_down_sync(0xFFFFFFFFu, s1, o);
            s2 += __shfl_down_sync(0xFFFFFFFFu, s2, o);
        }
        if (!lane) { asv[r] = s1; adv[r] = s2; }
    }
    __syncthreads();

    const float a = asv[tid], d = adv[tid];
    const float p = expf(a), qq = expf(0.2f * a);
    const float c1 = expf(d), c2 = expf(0.2f * d);
    pexp[tid] = p; qexp[tid] = qq;
    __syncthreads();

    const float th = -d;
    int rank = 0, k = 0;
    float Sp = 0.f, Sq = 0.f;
    for (int t = 0; t < 256; ++t) {
        float at = asv[t];
        rank += (at < a) || (at == a && t < tid);
        bool le = (at <= th);
        k += le;
        Sp += le ? 0.f : pexp[t];
        Sq += le ? qexp[t] : 0.f;
    }
    const int base = bh << 8;
    g_sidx[base + rank]  = tid;
    g_psort[base + rank] = p;
    g_qsort[base + rank] = qq;
    g_kpos[base + tid]   = k;
    g_rden[base + tid]   = 1.0f / fmaf(c1, Sp, c2 * Sq);
    g_e1[base + tid]     = c1;
    g_e2[base + tid]     = c2;
}

// ============================================================================
// K2b: aggregation per (b,h,dim-half). 2048 blocks x 256 threads, ~110 KB smem
// (2 CTAs/SM). Chunk-4 sums -> scans -> outputs with <=3 corrections.
// ============================================================================
#define HS2 68          // 64 dims + 4 pad (keeps 16B alignment)
#define NCH 64          // chunks of 4 sorted senders

__global__ void __launch_bounds__(256) gat1_aggr() {
    const int bh = blockIdx.x >> 1;         // b*4+hh
    const int half = blockIdx.x & 1;
    const int b = bh >> 2, hh = bh & 3;
    const int tid = threadIdx.x;

    extern __shared__ float sm[];
    float* hsm   = sm;                      // 256*68 = 17408
    float* sSuf  = hsm + 256 * HS2;         // 65*64 = 4160
    float* sPre  = sSuf + 65 * 64;          // 4160
    float* psort = sPre + 65 * 64;          // 256
    float* qsort = psort + 256;             // 256
    int*   sidx  = (int*)(qsort + 256);     // 256
    int*   kpos  = sidx + 256;              // 256
    float* e1    = (float*)(kpos + 256);    // 256
    float* e2    = e1 + 256;                // 256
    float* rden  = e2 + 256;                // 256

    const int base = bh << 8;
    psort[tid] = g_psort[base + tid];
    qsort[tid] = g_qsort[base + tid];
    sidx[tid]  = g_sidx[base + tid];
    kpos[tid]  = g_kpos[base + tid];
    e1[tid]    = g_e1[base + tid];
    e2[tid]    = g_e2[base + tid];
    rden[tid]  = g_rden[base + tid];

    // load h half-tile: 256 rows x 64 dims (16 float4 per row)
    const float* hbase = g_h1 + (size_t)(b * 256) * 512 + hh * 128 + half * 64;
#pragma unroll
    for (int i = 0; i < 16; ++i) {
        int idx = tid + (i << 8);           // 0..4095 float4 units
        int j = idx >> 4, q4 = (idx & 15) << 2;
        *(float4*)(hsm + j * HS2 + q4) = *(const float4*)(hbase + (size_t)j * 512 + q4);
    }
    __syncthreads();

    // chunk sums: 64 chunks x 64 dims
#pragma unroll
    for (int i = 0; i < 16; ++i) {
        int idx = tid + (i << 8);
        int c = idx >> 6, d = idx & 63;
        float sp = 0.f, sq = 0.f;
#pragma unroll
        for (int u = 0; u < 4; ++u) {
            int t = (c << 2) + u;
            float hv = hsm[sidx[t] * HS2 + d];
            sp = fmaf(psort[t], hv, sp);
            sq = fmaf(qsort[t], hv, sq);
        }
        sSuf[c * 64 + d] = sp;
        sPre[c * 64 + d] = sq;
    }
    __syncthreads();

    // scans over chunks: threads 0-63 suffix(P), 64-127 prefix(Q)
    if (tid < 128) {
        int d = tid & 63;
        if (tid < 64) {
            float val = 0.f;
            sSuf[NCH * 64 + d] = 0.f;
            for (int c = NCH - 1; c >= 0; --c) {
                val += sSuf[c * 64 + d];
                sSuf[c * 64 + d] = val;
            }
        } else {
            float val = 0.f;
            for (int c = 0; c < NCH; ++c) {
                float t = sPre[c * 64 + d];
                sPre[c * 64 + d] = val;
                val += t;
            }
            sPre[NCH * 64 + d] = val;
        }
    }
    __syncthreads();

    // outputs: group g (of 4) handles receivers g*64..g*64+63; thread owns dim d
    {
        const int g = tid >> 6, d = tid & 63;
        float* ob = g_out1 + (size_t)(b * 256) * 512 + hh * 128 + half * 64 + d;
        for (int ii = 0; ii < 64; ++ii) {
            int i = (g << 6) + ii;
            int k = kpos[i];
            int c = k >> 2;
            float suf = sSuf[c * 64 + d];
            float pre = sPre[c * 64 + d];
            for (int t = (c << 2); t < k; ++t) {
                float hv = hsm[sidx[t] * HS2 + d];
                suf = fmaf(-psort[t], hv, suf);
                pre = fmaf(qsort[t], hv, pre);
            }
            float num = fmaf(e1[i], suf, e2[i] * pre);
            ob[(size_t)i * 512] = num * rden[i];
        }
    }
}

// ============================================================================
// K3: LayerNorm + ELU + dot W2
// ============================================================================
__global__ void __launch_bounds__(128) ln_elu_z_kernel(const float* __restrict__ b1,
                                                       const float* __restrict__ gamma,
                                                       const float* __restrict__ beta,
                                                       const float* __restrict__ W2) {
    const int row = blockIdx.x;
    const int tid = threadIdx.x;
    const int lane = tid & 31, w = tid >> 5;
    __shared__ float red[16];

    const float* r = g_out1 + (size_t)row * 512;
    float4 v  = *(const float4*)(r + (tid << 2));
    float4 bb = *(const float4*)(b1 + (tid << 2));
    v.x += bb.x; v.y += bb.y; v.z += bb.z; v.w += bb.w;

    float s  = v.x + v.y + v.z + v.w;
    float sq = v.x * v.x + v.y * v.y + v.z * v.z + v.w * v.w;
#pragma unroll
    for (int o = 16; o > 0; o >>= 1) {
        s  += __shfl_down_sync(0xFFFFFFFFu, s, o);
        sq += __shfl_down_sync(0xFFFFFFFFu, sq, o);
    }
    if (!lane) { red[w] = s; red[8 + w] = sq; }
    __syncthreads();
    float st  = red[0] + red[1] + red[2] + red[3];
    float sqt = red[8] + red[9] + red[10] + red[11];
    float mu   = st * (1.0f / 512.0f);
    float var  = sqt * (1.0f / 512.0f) - mu * mu;
    float rstd = rsqrtf(var + 1e-5f);

    float4 g4 = *(const float4*)(gamma + (tid << 2));
    float4 be = *(const float4*)(beta + (tid << 2));
    float4 w4 = *(const float4*)(W2 + (tid << 2));

    float y0 = (v.x - mu) * rstd * g4.x + be.x; y0 = y0 > 0.f ? y0 : expm1f(y0);
    float y1 = (v.y - mu) * rstd * g4.y + be.y; y1 = y1 > 0.f ? y1 : expm1f(y1);
    float y2 = (v.z - mu) * rstd * g4.z + be.z; y2 = y2 > 0.f ? y2 : expm1f(y2);
    float y3 = (v.w - mu) * rstd * g4.w + be.w; y3 = y3 > 0.f ? y3 : expm1f(y3);

    float acc = y0 * w4.x + y1 * w4.y + y2 * w4.z + y3 * w4.w;
#pragma unroll
    for (int o = 16; o > 0; o >>= 1) acc += __shfl_down_sync(0xFFFFFFFFu, acc, o);
    __syncthreads();
    if (!lane) red[w] = acc;
    __syncthreads();
    if (!tid) g_z[row] = red[0] + red[1] + red[2] + red[3];
}

// ============================================================================
// K4: layer-2 scalar attention
// ============================================================================
__global__ void __launch_bounds__(256) gat2_attn_kernel(const float* __restrict__ s_src,
                                                        const float* __restrict__ s_dst,
                                                        const float* __restrict__ b2,
                                                        float* __restrict__ out) {
    const int b = blockIdx.x;
    const int tid = threadIdx.x;
    __shared__ float zs[256], asx[256];
    float zv = g_z[b * 256 + tid];
    float ssc = s_src[0], sdc = s_dst[0];
    zs[tid] = zv;
    asx[tid] = zv * ssc;
    __syncthreads();
    float adi = zv * sdc;
    float num = 0.f, den = 0.f;
    for (int j = 0; j < 256; ++j) {
        float e = adi + asx[j];
        e = e > 0.f ? e : 0.2f * e;
        float wgt = expf(e);
        num = fmaf(wgt, zs[j], num);
        den += wgt;
    }
    out[b * 256 + tid] = num / den + b2[0];
}

// ============================================================================
// launch
// ============================================================================
extern "C" void kernel_launch(void* const* d_in, const int* in_sizes, int n_in,
                              void* d_out, int out_size) {
    const float* x     = (const float*)d_in[0];
    const float* W1    = (const float*)d_in[2];
    const float* as1   = (const float*)d_in[3];
    const float* ad1   = (const float*)d_in[4];
    const float* b1    = (const float*)d_in[5];
    const float* gamma = (const float*)d_in[6];
    const float* beta  = (const float*)d_in[7];
    const float* W2    = (const float*)d_in[8];
    const float* as2   = (const float*)d_in[9];
    const float* ad2   = (const float*)d_in[10];
    const float* b2    = (const float*)d_in[11];
    float* out = (float*)d_out;

    const int smem_gemm = 4 * ABUF;                                   // 65536
    const int smem_aggr = (256 * HS2 + 2 * 65 * 64 + 7 * 256) * 4;    // 110080
    cudaFuncSetAttribute(gemm_k1, cudaFuncAttributeMaxDynamicSharedMemorySize, smem_gemm);
    cudaFuncSetAttribute(gat1_aggr, cudaFuncAttributeMaxDynamicSharedMemorySize, smem_aggr);

    conv_x<<<8192, 256>>>(x);
    conv_w<<<512, 128>>>(W1);
    gemm_k1<<<2048, 256, smem_gemm>>>();
    gat1_scalars<<<Bsz * Hh, 256>>>(as1, ad1);
    gat1_aggr<<<Bsz * Hh * 2, 256, smem_aggr>>>();
    ln_elu_z_kernel<<<Bsz * Nn, 128>>>(b1, gamma, beta, W2);
    gat2_attn_kernel<<<Bsz, 256>>>(as2, ad2, b2, out);
}

// round 8
// speedup vs baseline: 1.8015x; 1.0260x over previous
#include <cuda_runtime.h>
#include <cuda_bf16.h>
#include <math.h>
#include <stdint.h>

// GAT2: B=256, N=256, DIN=128, H=4, DH=128.
//   conv_x/conv_w: split fp32 -> bf16 hi/lo, packed K=384 (x*W = xh*Wh + xh*Wl + xl*Wh)
//   K1 : mma.sync (HMMA) bf16 GEMM 65536x512, K=384, fp32 accum.
//        Epilogue ALSO computes as/ad attention dots (CTA tile = one head) -> g_as/g_ad.
//   K2r: per-(b,h) rank-by-count scalars (reads only as/ad; 2 MB traffic)
//   K2b: per-(b,h,dim-half) aggregation via chunk-4 prefix/suffix sums
//   K3 : LayerNorm + ELU + dot W2 -> z
//   K4 : layer-2 scalar attention

#define Bsz 256
#define Nn  256
#define Hh  4
#define HD  512
#define KP  384
#define MTOT 65536

__device__ __nv_bfloat16 g_A[(size_t)MTOT * KP];   // 50 MB packed x
__device__ __nv_bfloat16 g_Bm[(size_t)HD * KP];    // 393 KB packed W (N-major)
__device__ float g_h1[(size_t)MTOT * HD];          // 134 MB
__device__ float g_out1[(size_t)MTOT * HD];        // 134 MB
__device__ float g_z[Bsz * Nn];
__device__ float g_as[Bsz * Hh * 256];
__device__ float g_ad[Bsz * Hh * 256];

// K2 scalar interchange arrays (per (b,h): 256 entries)
__device__ int   g_sidx[Bsz * Hh * 256];
__device__ float g_psort[Bsz * Hh * 256];
__device__ float g_qsort[Bsz * Hh * 256];
__device__ int   g_kpos[Bsz * Hh * 256];
__device__ float g_rden[Bsz * Hh * 256];
__device__ float g_e1[Bsz * Hh * 256];
__device__ float g_e2[Bsz * Hh * 256];

__device__ __forceinline__ uint32_t smem_u32(const void* p) {
    uint32_t a;
    asm("{ .reg .u64 t; cvta.to.shared.u64 t, %1; cvt.u32.u64 %0, t; }" : "=r"(a) : "l"(p));
    return a;
}

// ============================================================================
// conversion kernels: fp32 -> packed split-bf16
// ============================================================================
__global__ void __launch_bounds__(256) conv_x(const float* __restrict__ x) {
    int idx = blockIdx.x * 256 + threadIdx.x;
    int m = idx >> 5, j4 = (idx & 31) << 2;
    float4 v = *(const float4*)(x + (size_t)m * 128 + j4);
    __nv_bfloat16 h[4], l[4];
    float vv[4] = {v.x, v.y, v.z, v.w};
#pragma unroll
    for (int i = 0; i < 4; ++i) {
        h[i] = __float2bfloat16_rn(vv[i]);
        l[i] = __float2bfloat16_rn(vv[i] - __bfloat162float(h[i]));
    }
    __nv_bfloat16* dst = g_A + (size_t)m * KP + j4;
    *(uint2*)(dst)       = *(uint2*)h;
    *(uint2*)(dst + 128) = *(uint2*)h;
    *(uint2*)(dst + 256) = *(uint2*)l;
}
__global__ void __launch_bounds__(128) conv_w(const float* __restrict__ W1) {
    int n = blockIdx.x, k = threadIdx.x;
    float w = W1[(size_t)k * HD + n];
    __nv_bfloat16 hi = __float2bfloat16_rn(w);
    __nv_bfloat16 lo = __float2bfloat16_rn(w - __bfloat162float(hi));
    __nv_bfloat16* dst = g_Bm + (size_t)n * KP;
    dst[k] = hi; dst[128 + k] = lo; dst[256 + k] = hi;
}

// ============================================================================
// K1: HMMA GEMM + fused attention-dot epilogue.
// CTA tile 128x128 (= one head), 8 warps (2M x 4N), BK=64 double-buffered.
// ============================================================================
#define BK 64
#define NCHUNK 6
#define ABUF 16384

__device__ __forceinline__ void cpa16(uint32_t dst, const void* src) {
    asm volatile("cp.async.cg.shared.global [%0], [%1], 16;" :: "r"(dst), "l"(src));
}
__device__ __forceinline__ void load_chunk(uint32_t sA, uint32_t sB,
                                           const __nv_bfloat16* gA, const __nv_bfloat16* gB,
                                           int kc, int tid) {
    int r = tid >> 1, half = tid & 1;
    const __nv_bfloat16* ga = gA + (size_t)r * KP + kc * BK + half * 32;
    const __nv_bfloat16* gb = gB + (size_t)r * KP + kc * BK + half * 32;
    uint32_t rowoff = (uint32_t)r << 7;
    int sx = r & 7;
#pragma unroll
    for (int i = 0; i < 4; ++i) {
        int c = half * 4 + i;
        uint32_t sw = rowoff + ((uint32_t)(c ^ sx) << 4);
        cpa16(sA + sw, ga + i * 8);
        cpa16(sB + sw, gb + i * 8);
    }
    asm volatile("cp.async.commit_group;" ::: "memory");
}

__global__ void __launch_bounds__(256, 2) gemm_k1(const float* __restrict__ att_src,
                                                  const float* __restrict__ att_dst) {
    extern __shared__ char dyn[];
    __shared__ float sSrc[128], sDst[128];
    __shared__ float sAsW[4][128], sAdW[4][128];

    const int tid = threadIdx.x;
    const int wid = tid >> 5, lane = tid & 31;
    const int wm = wid & 1, wn = wid >> 1;
    const int mt = blockIdx.x >> 2, nt = blockIdx.x & 3;
    const int m0 = mt << 7, n0 = nt << 7;

    if (tid < 128) {
        sSrc[tid] = att_src[nt * 128 + tid];
        sDst[tid] = att_dst[nt * 128 + tid];
    }

    uint32_t sb = smem_u32(dyn);
    const __nv_bfloat16* gA = g_A + (size_t)m0 * KP;
    const __nv_bfloat16* gB = g_Bm + (size_t)n0 * KP;

    float acc[4][4][4];
#pragma unroll
    for (int i = 0; i < 4; ++i)
#pragma unroll
        for (int j = 0; j < 4; ++j)
#pragma unroll
            for (int k = 0; k < 4; ++k) acc[i][j][k] = 0.f;

    const int arow = wm * 64 + (lane & 15);
    const int brow = wn * 32 + (lane & 15);
    const int cs = lane >> 4;
    const int asx = arow & 7, bsx = brow & 7;

    load_chunk(sb, sb + 2 * ABUF, gA, gB, 0, tid);

    int buf = 0;
    for (int kc = 0; kc < NCHUNK; ++kc) {
        if (kc < NCHUNK - 1)
            load_chunk(sb + (buf ^ 1) * ABUF, sb + 2 * ABUF + (buf ^ 1) * ABUF, gA, gB, kc + 1, tid);
        if (kc < NCHUNK - 1) asm volatile("cp.async.wait_group 1;" ::: "memory");
        else                 asm volatile("cp.async.wait_group 0;" ::: "memory");
        __syncthreads();

        uint32_t Ab = sb + buf * ABUF;
        uint32_t Bb = sb + 2 * ABUF + buf * ABUF;
#pragma unroll
        for (int ks = 0; ks < 4; ++ks) {
            uint32_t a[4][4], bfr[4][2];
#pragma unroll
            for (int ti = 0; ti < 4; ++ti) {
                uint32_t addr = Ab + ((uint32_t)(arow + ti * 16) << 7)
                              + ((uint32_t)((ks * 2 + cs) ^ asx) << 4);
                asm volatile("ldmatrix.sync.aligned.m8n8.x4.shared.b16 {%0,%1,%2,%3}, [%4];"
                    : "=r"(a[ti][0]), "=r"(a[ti][1]), "=r"(a[ti][2]), "=r"(a[ti][3]) : "r"(addr));
            }
#pragma unroll
            for (int tjp = 0; tjp < 2; ++tjp) {
                uint32_t q0, q1, q2, q3;
                uint32_t addr = Bb + ((uint32_t)(brow + tjp * 16) << 7)
                              + ((uint32_t)((ks * 2 + cs) ^ bsx) << 4);
                asm volatile("ldmatrix.sync.aligned.m8n8.x4.shared.b16 {%0,%1,%2,%3}, [%4];"
                    : "=r"(q0), "=r"(q1), "=r"(q2), "=r"(q3) : "r"(addr));
                bfr[tjp * 2][0] = q0;     bfr[tjp * 2][1] = q2;
                bfr[tjp * 2 + 1][0] = q1; bfr[tjp * 2 + 1][1] = q3;
            }
#pragma unroll
            for (int ti = 0; ti < 4; ++ti)
#pragma unroll
                for (int tj = 0; tj < 4; ++tj)
                    asm volatile(
                        "mma.sync.aligned.m16n8k16.row.col.f32.bf16.bf16.f32 "
                        "{%0,%1,%2,%3}, {%4,%5,%6,%7}, {%8,%9}, {%0,%1,%2,%3};"
                        : "+f"(acc[ti][tj][0]), "+f"(acc[ti][tj][1]),
                          "+f"(acc[ti][tj][2]), "+f"(acc[ti][tj][3])
                        : "r"(a[ti][0]), "r"(a[ti][1]), "r"(a[ti][2]), "r"(a[ti][3]),
                          "r"(bfr[tj][0]), "r"(bfr[tj][1]));
        }
        __syncthreads();
        buf ^= 1;
    }

    // ---- epilogue: store h1 + fused as/ad dots ----
    const int q = lane >> 2, p2 = (lane & 3) << 1;
#pragma unroll
    for (int ti = 0; ti < 4; ++ti) {
        int m = m0 + wm * 64 + ti * 16 + q;
        float pa0 = 0.f, pa1 = 0.f, pd0 = 0.f, pd1 = 0.f;
#pragma unroll
        for (int tj = 0; tj < 4; ++tj) {
            int n = n0 + wn * 32 + tj * 8 + p2;
            *(float2*)(g_h1 + (size_t)m * HD + n)       = make_float2(acc[ti][tj][0], acc[ti][tj][1]);
            *(float2*)(g_h1 + (size_t)(m + 8) * HD + n) = make_float2(acc[ti][tj][2], acc[ti][tj][3]);
            int c0 = wn * 32 + tj * 8 + p2;
            float s0 = sSrc[c0], s1 = sSrc[c0 + 1];
            float d0 = sDst[c0], d1 = sDst[c0 + 1];
            pa0 = fmaf(acc[ti][tj][0], s0, fmaf(acc[ti][tj][1], s1, pa0));
            pd0 = fmaf(acc[ti][tj][0], d0, fmaf(acc[ti][tj][1], d1, pd0));
            pa1 = fmaf(acc[ti][tj][2], s0, fmaf(acc[ti][tj][3], s1, pa1));
            pd1 = fmaf(acc[ti][tj][2], d0, fmaf(acc[ti][tj][3], d1, pd1));
        }
        // reduce across the 4 lanes sharing this row (differ only in p2)
        pa0 += __shfl_xor_sync(0xFFFFFFFFu, pa0, 1); pa0 += __shfl_xor_sync(0xFFFFFFFFu, pa0, 2);
        pd0 += __shfl_xor_sync(0xFFFFFFFFu, pd0, 1); pd0 += __shfl_xor_sync(0xFFFFFFFFu, pd0, 2);
        pa1 += __shfl_xor_sync(0xFFFFFFFFu, pa1, 1); pa1 += __shfl_xor_sync(0xFFFFFFFFu, pa1, 2);
        pd1 += __shfl_xor_sync(0xFFFFFFFFu, pd1, 1); pd1 += __shfl_xor_sync(0xFFFFFFFFu, pd1, 2);
        if ((lane & 3) == 0) {
            int r = wm * 64 + ti * 16 + q;
            sAsW[wn][r] = pa0; sAdW[wn][r] = pd0;
            sAsW[wn][r + 8] = pa1; sAdW[wn][r + 8] = pd1;
        }
    }
    __syncthreads();
    if (tid < 128) {
        int b = m0 >> 8, nl0 = m0 & 255;
        int gi = ((b * 4 + nt) << 8) + nl0 + tid;
        g_as[gi] = (sAsW[0][tid] + sAsW[1][tid]) + (sAsW[2][tid] + sAsW[3][tid]);
        g_ad[gi] = (sAdW[0][tid] + sAdW[1][tid]) + (sAdW[2][tid] + sAdW[3][tid]);
    }
}

// ============================================================================
// K2r: per-(b,h) rank-by-count scalars (reads only g_as/g_ad).
// ============================================================================
__global__ void __launch_bounds__(256) gat1_rank() {
    const int bh = blockIdx.x;
    const int tid = threadIdx.x;
    __shared__ float asv[256], adv[256], pexp[256], qexp[256];

    const int base = bh << 8;
    const float a = g_as[base + tid];
    const float d = g_ad[base + tid];
    asv[tid] = a; adv[tid] = d;
    const float p = expf(a), qq = expf(0.2f * a);
    const float c1 = expf(d), c2 = expf(0.2f * d);
    pexp[tid] = p; qexp[tid] = qq;
    __syncthreads();

    const float th = -d;
    int rank = 0, k = 0;
    float Sp = 0.f, Sq = 0.f;
    for (int t = 0; t < 256; ++t) {
        float at = asv[t];
        rank += (at < a) || (at == a && t < tid);
        bool le = (at <= th);
        k += le;
        Sp += le ? 0.f : pexp[t];
        Sq += le ? qexp[t] : 0.f;
    }
    g_sidx[base + rank]  = tid;
    g_psort[base + rank] = p;
    g_qsort[base + rank] = qq;
    g_kpos[base + tid]   = k;
    g_rden[base + tid]   = 1.0f / fmaf(c1, Sp, c2 * Sq);
    g_e1[base + tid]     = c1;
    g_e2[base + tid]     = c2;
}

// ============================================================================
// K2b: aggregation per (b,h,dim-half). 2048 blocks x 256 threads, ~110 KB smem
// ============================================================================
#define HS2 68
#define NCH 64

__global__ void __launch_bounds__(256) gat1_aggr() {
    const int bh = blockIdx.x >> 1;
    const int half = blockIdx.x & 1;
    const int b = bh >> 2, hh = bh & 3;
    const int tid = threadIdx.x;

    extern __shared__ float sm[];
    float* hsm   = sm;                      // 256*68
    float* sSuf  = hsm + 256 * HS2;         // 65*64
    float* sPre  = sSuf + 65 * 64;          // 65*64
    float* psort = sPre + 65 * 64;          // 256
    float* qsort = psort + 256;             // 256
    int*   sidx  = (int*)(qsort + 256);     // 256
    int*   kpos  = sidx + 256;              // 256
    float* e1    = (float*)(kpos + 256);    // 256
    float* e2    = e1 + 256;                // 256
    float* rden  = e2 + 256;                // 256

    const int base = bh << 8;
    psort[tid] = g_psort[base + tid];
    qsort[tid] = g_qsort[base + tid];
    sidx[tid]  = g_sidx[base + tid];
    kpos[tid]  = g_kpos[base + tid];
    e1[tid]    = g_e1[base + tid];
    e2[tid]    = g_e2[base + tid];
    rden[tid]  = g_rden[base + tid];

    const float* hbase = g_h1 + (size_t)(b * 256) * 512 + hh * 128 + half * 64;
#pragma unroll
    for (int i = 0; i < 16; ++i) {
        int idx = tid + (i << 8);
        int j = idx >> 4, q4 = (idx & 15) << 2;
        *(float4*)(hsm + j * HS2 + q4) = *(const float4*)(hbase + (size_t)j * 512 + q4);
    }
    __syncthreads();

#pragma unroll
    for (int i = 0; i < 16; ++i) {
        int idx = tid + (i << 8);
        int c = idx >> 6, d = idx & 63;
        float sp = 0.f, sq = 0.f;
#pragma unroll
        for (int u = 0; u < 4; ++u) {
            int t = (c << 2) + u;
            float hv = hsm[sidx[t] * HS2 + d];
            sp = fmaf(psort[t], hv, sp);
            sq = fmaf(qsort[t], hv, sq);
        }
        sSuf[c * 64 + d] = sp;
        sPre[c * 64 + d] = sq;
    }
    __syncthreads();

    if (tid < 128) {
        int d = tid & 63;
        if (tid < 64) {
            float val = 0.f;
            sSuf[NCH * 64 + d] = 0.f;
            for (int c = NCH - 1; c >= 0; --c) {
                val += sSuf[c * 64 + d];
                sSuf[c * 64 + d] = val;
            }
        } else {
            float val = 0.f;
            for (int c = 0; c < NCH; ++c) {
                float t = sPre[c * 64 + d];
                sPre[c * 64 + d] = val;
                val += t;
            }
            sPre[NCH * 64 + d] = val;
        }
    }
    __syncthreads();

    {
        const int g = tid >> 6, d = tid & 63;
        float* ob = g_out1 + (size_t)(b * 256) * 512 + hh * 128 + half * 64 + d;
        for (int ii = 0; ii < 64; ++ii) {
            int i = (g << 6) + ii;
            int k = kpos[i];
            int c = k >> 2;
            float suf = sSuf[c * 64 + d];
            float pre = sPre[c * 64 + d];
            for (int t = (c << 2); t < k; ++t) {
                float hv = hsm[sidx[t] * HS2 + d];
                suf = fmaf(-psort[t], hv, suf);
                pre = fmaf(qsort[t], hv, pre);
            }
            float num = fmaf(e1[i], suf, e2[i] * pre);
            ob[(size_t)i * 512] = num * rden[i];
        }
    }
}

// ============================================================================
// K3: LayerNorm + ELU + dot W2
// ============================================================================
__global__ void __launch_bounds__(128) ln_elu_z_kernel(const float* __restrict__ b1,
                                                       const float* __restrict__ gamma,
                                                       const float* __restrict__ beta,
                                                       const float* __restrict__ W2) {
    const int row = blockIdx.x;
    const int tid = threadIdx.x;
    const int lane = tid & 31, w = tid >> 5;
    __shared__ float red[16];

    const float* r = g_out1 + (size_t)row * 512;
    float4 v  = *(const float4*)(r + (tid << 2));
    float4 bb = *(const float4*)(b1 + (tid << 2));
    v.x += bb.x; v.y += bb.y; v.z += bb.z; v.w += bb.w;

    float s  = v.x + v.y + v.z + v.w;
    float sq = v.x * v.x + v.y * v.y + v.z * v.z + v.w * v.w;
#pragma unroll
    for (int o = 16; o > 0; o >>= 1) {
        s  += __shfl_down_sync(0xFFFFFFFFu, s, o);
        sq += __shfl_down_sync(0xFFFFFFFFu, sq, o);
    }
    if (!lane) { red[w] = s; red[8 + w] = sq; }
    __syncthreads();
    float st  = red[0] + red[1] + red[2] + red[3];
    float sqt = red[8] + red[9] + red[10] + red[11];
    float mu   = st * (1.0f / 512.0f);
    float var  = sqt * (1.0f / 512.0f) - mu * mu;
    float rstd = rsqrtf(var + 1e-5f);

    float4 g4 = *(const float4*)(gamma + (tid << 2));
    float4 be = *(const float4*)(beta + (tid << 2));
    float4 w4 = *(const float4*)(W2 + (tid << 2));

    float y0 = (v.x - mu) * rstd * g4.x + be.x; y0 = y0 > 0.f ? y0 : expm1f(y0);
    float y1 = (v.y - mu) * rstd * g4.y + be.y; y1 = y1 > 0.f ? y1 : expm1f(y1);
    float y2 = (v.z - mu) * rstd * g4.z + be.z; y2 = y2 > 0.f ? y2 : expm1f(y2);
    float y3 = (v.w - mu) * rstd * g4.w + be.w; y3 = y3 > 0.f ? y3 : expm1f(y3);

    float acc = y0 * w4.x + y1 * w4.y + y2 * w4.z + y3 * w4.w;
#pragma unroll
    for (int o = 16; o > 0; o >>= 1) acc += __shfl_down_sync(0xFFFFFFFFu, acc, o);
    __syncthreads();
    if (!lane) red[w] = acc;
    __syncthreads();
    if (!tid) g_z[row] = red[0] + red[1] + red[2] + red[3];
}

// ============================================================================
// K4: layer-2 scalar attention
// ============================================================================
__global__ void __launch_bounds__(256) gat2_attn_kernel(const float* __restrict__ s_src,
                                                        const float* __restrict__ s_dst,
                                                        const float* __restrict__ b2,
                                                        float* __restrict__ out) {
    const int b = blockIdx.x;
    const int tid = threadIdx.x;
    __shared__ float zs[256], asx[256];
    float zv = g_z[b * 256 + tid];
    float ssc = s_src[0], sdc = s_dst[0];
    zs[tid] = zv;
    asx[tid] = zv * ssc;
    __syncthreads();
    float adi = zv * sdc;
    float num = 0.f, den = 0.f;
    for (int j = 0; j < 256; ++j) {
        float e = adi + asx[j];
        e = e > 0.f ? e : 0.2f * e;
        float wgt = expf(e);
        num = fmaf(wgt, zs[j], num);
        den += wgt;
    }
    out[b * 256 + tid] = num / den + b2[0];
}

// ============================================================================
// launch
// ============================================================================
extern "C" void kernel_launch(void* const* d_in, const int* in_sizes, int n_in,
                              void* d_out, int out_size) {
    const float* x     = (const float*)d_in[0];
    const float* W1    = (const float*)d_in[2];
    const float* as1   = (const float*)d_in[3];
    const float* ad1   = (const float*)d_in[4];
    const float* b1    = (const float*)d_in[5];
    const float* gamma = (const float*)d_in[6];
    const float* beta  = (const float*)d_in[7];
    const float* W2    = (const float*)d_in[8];
    const float* as2   = (const float*)d_in[9];
    const float* ad2   = (const float*)d_in[10];
    const float* b2    = (const float*)d_in[11];
    float* out = (float*)d_out;

    const int smem_gemm = 4 * ABUF;                                   // 65536
    const int smem_aggr = (256 * HS2 + 2 * 65 * 64 + 7 * 256) * 4;    // 110080
    cudaFuncSetAttribute(gemm_k1, cudaFuncAttributeMaxDynamicSharedMemorySize, smem_gemm);
    cudaFuncSetAttribute(gat1_aggr, cudaFuncAttributeMaxDynamicSharedMemorySize, smem_aggr);

    conv_x<<<8192, 256>>>(x);
    conv_w<<<512, 128>>>(W1);
    gemm_k1<<<2048, 256, smem_gemm>>>(as1, ad1);
    gat1_rank<<<Bsz * Hh, 256>>>();
    gat1_aggr<<<Bsz * Hh * 2, 256, smem_aggr>>>();
    ln_elu_z_kernel<<<Bsz * Nn, 128>>>(b1, gamma, beta, W2);
    gat2_attn_kernel<<<Bsz, 256>>>(as2, ad2, b2, out);
}